// round 1
// baseline (speedup 1.0000x reference)
#include <cuda_runtime.h>
#include <cuda_bf16.h>
#include <cstdint>

// Problem constants (fixed by the dataset)
#define DIM 128
#define B_FIX 256
#define N_FIX 131072
#define KK 8            // compile-time top-k capacity (num_neg <= 8)

// Scratch: full similarity matrix, 256 x 131072 fp32 = 134 MB (static __device__, no alloc)
__device__ float g_sim[(size_t)B_FIX * N_FIX];

// ---------------------------------------------------------------------------
// Kernel 0: zero the scalar output
// ---------------------------------------------------------------------------
__global__ void prep_kernel(float* out) {
    if (threadIdx.x == 0 && blockIdx.x == 0) out[0] = 0.0f;
}

// ---------------------------------------------------------------------------
// Kernel 1: sim = X @ Y^T   (X: [B,128], Y: [N,128], both K-major / row-major)
// Tile: 128x128 per block, BK=16, 256 threads, 8x8 register tile per thread.
// ---------------------------------------------------------------------------
__global__ __launch_bounds__(256) void gemm_kernel(
    const float* __restrict__ X, const float* __restrict__ Y, int N)
{
    __shared__ float Xs[16][132];   // padded: (k*132+row) % 32 varies with k -> low conflicts
    __shared__ float Ys[16][132];

    const int bn0 = blockIdx.x * 128;
    const int bm0 = blockIdx.y * 128;
    const int t   = threadIdx.x;
    const int tx  = t & 15;   // n-direction (16 threads)
    const int ty  = t >> 4;   // m-direction (16 threads)

    float acc[8][8];
#pragma unroll
    for (int i = 0; i < 8; i++)
#pragma unroll
        for (int j = 0; j < 8; j++) acc[i][j] = 0.0f;

    const int r0 = t >> 2;    // 0..63 : row within half-tile
    const int c4 = t & 3;     // which float4 of the 16-wide K slice

    for (int kt = 0; kt < DIM; kt += 16) {
#pragma unroll
        for (int h = 0; h < 2; h++) {
            int row = r0 + h * 64;
            float4 v = *reinterpret_cast<const float4*>(
                X + (size_t)(bm0 + row) * DIM + kt + c4 * 4);
            Xs[c4 * 4 + 0][row] = v.x;
            Xs[c4 * 4 + 1][row] = v.y;
            Xs[c4 * 4 + 2][row] = v.z;
            Xs[c4 * 4 + 3][row] = v.w;
            float4 w = *reinterpret_cast<const float4*>(
                Y + (size_t)(bn0 + row) * DIM + kt + c4 * 4);
            Ys[c4 * 4 + 0][row] = w.x;
            Ys[c4 * 4 + 1][row] = w.y;
            Ys[c4 * 4 + 2][row] = w.z;
            Ys[c4 * 4 + 3][row] = w.w;
        }
        __syncthreads();

#pragma unroll
        for (int k = 0; k < 16; k++) {
            float a[8], b[8];
            *reinterpret_cast<float4*>(&a[0]) =
                *reinterpret_cast<const float4*>(&Xs[k][ty * 8]);
            *reinterpret_cast<float4*>(&a[4]) =
                *reinterpret_cast<const float4*>(&Xs[k][ty * 8 + 4]);
            *reinterpret_cast<float4*>(&b[0]) =
                *reinterpret_cast<const float4*>(&Ys[k][tx * 8]);
            *reinterpret_cast<float4*>(&b[4]) =
                *reinterpret_cast<const float4*>(&Ys[k][tx * 8 + 4]);
#pragma unroll
            for (int i = 0; i < 8; i++)
#pragma unroll
                for (int j = 0; j < 8; j++)
                    acc[i][j] = fmaf(a[i], b[j], acc[i][j]);
        }
        __syncthreads();
    }

    // Write the 8x8 tile (two float4 stores per row)
#pragma unroll
    for (int i = 0; i < 8; i++) {
        size_t row = (size_t)(bm0 + ty * 8 + i);
        float* cp = g_sim + row * (size_t)N + bn0 + tx * 8;
        *reinterpret_cast<float4*>(cp) =
            make_float4(acc[i][0], acc[i][1], acc[i][2], acc[i][3]);
        *reinterpret_cast<float4*>(cp + 4) =
            make_float4(acc[i][4], acc[i][5], acc[i][6], acc[i][7]);
    }
}

// ---------------------------------------------------------------------------
// Kernel 2: per-row (find pos from target) -> top-num_neg of sim excluding pos
//           -> hinge loss + masked softmax -> atomicAdd of the mean contribution
// One block per row b, 256 threads.
// ---------------------------------------------------------------------------
__global__ __launch_bounds__(256) void topk_loss_kernel(
    const float* __restrict__ target,
    const int*   __restrict__ numneg_ptr,   // may be null
    float* __restrict__ out, int N, int Btot)
{
    const int b = blockIdx.x;
    const int t = threadIdx.x;

    int num_neg = 5;
    if (numneg_ptr) {
        int nn = *numneg_ptr;          // low 32 bits; valid for int32 or int64 scalar
        if (nn >= 1 && nn <= KK) num_neg = nn;
    }

    // --- find positive index from target row (dtype-robust vs pos_inds) ---
    __shared__ int s_pos;
    if (t == 0) s_pos = 0;
    __syncthreads();
    const float* trow = target + (size_t)b * N;
    for (int i = t; i < N; i += 256) {
        if (trow[i] >= 1e-6f) atomicMax(&s_pos, i);
    }
    __syncthreads();
    const int pos = s_pos;

    // --- per-thread top-KK over the sim row, excluding pos ---
    const float* srow = g_sim + (size_t)b * N;
    float tv[KK];
#pragma unroll
    for (int i = 0; i < KK; i++) tv[i] = -3.0e38f;

    for (int i = t; i < N; i += 256) {
        float v = srow[i];
        if (i == pos) continue;
        if (v > tv[KK - 1]) {
            tv[KK - 1] = v;
#pragma unroll
            for (int j = KK - 1; j > 0; j--) {
                if (tv[j] > tv[j - 1]) {
                    float tmp = tv[j]; tv[j] = tv[j - 1]; tv[j - 1] = tmp;
                }
            }
        }
    }

    // --- block reduction: select the global top num_neg values ---
    __shared__ float sv[256 * KK];
    __shared__ float s_red[256];
    __shared__ int   s_idx[256];
    __shared__ float s_top[KK];
#pragma unroll
    for (int i = 0; i < KK; i++) sv[t * KK + i] = tv[i];
    __syncthreads();

    for (int r = 0; r < num_neg; r++) {
        float bv = sv[t * KK];
        int   bi = t * KK;
#pragma unroll
        for (int i = 1; i < KK; i++) {
            float v = sv[t * KK + i];
            if (v > bv) { bv = v; bi = t * KK + i; }
        }
        s_red[t] = bv;
        s_idx[t] = bi;
        __syncthreads();
        for (int s = 128; s > 0; s >>= 1) {
            if (t < s && s_red[t + s] > s_red[t]) {
                s_red[t] = s_red[t + s];
                s_idx[t] = s_idx[t + s];
            }
            __syncthreads();
        }
        if (t == 0) {
            s_top[r] = s_red[0];
            sv[s_idx[0]] = -3.0e38f;
        }
        __syncthreads();
    }

    // --- epilogue: hinge + masked softmax, exactly matching the reference ---
    if (t == 0) {
        float sim_p = srow[pos];
        float loss[KK], m[KK];
        float mx = -3.0e38f;
        for (int r = 0; r < num_neg; r++) {
            float sn = s_top[r];
            float l  = sn - sim_p + 0.3f;
            l = (l > 0.0f) ? l : 0.0f;
            float mm = (l != 0.0f) ? sn : 0.0f;   // sim_n * mask
            loss[r] = l;
            m[r]    = mm;
            if (mm > mx) mx = mm;
        }
        float ssum = 0.0f, res = 0.0f;
        float e[KK];
        for (int r = 0; r < num_neg; r++) {
            e[r] = expf(m[r] - mx);
            ssum += e[r];
        }
        for (int r = 0; r < num_neg; r++) res += loss[r] * e[r];
        res /= ssum;                                // sum(loss * prob) for this row
        atomicAdd(out, res / ((float)Btot * (float)num_neg));
    }
}

// ---------------------------------------------------------------------------
// kernel_launch
// ---------------------------------------------------------------------------
extern "C" void kernel_launch(void* const* d_in, const int* in_sizes, int n_in,
                              void* d_out, int out_size)
{
    const float* xembs  = (const float*)d_in[0];
    const float* yembs  = (const float*)d_in[1];
    const float* target = (const float*)d_in[2];
    const int*   numneg = (n_in >= 5) ? (const int*)d_in[4] : nullptr;

    const int B = in_sizes[0] / DIM;   // 256
    const int N = in_sizes[1] / DIM;   // 131072
    float* out = (float*)d_out;

    prep_kernel<<<1, 32>>>(out);

    dim3 grid(N / 128, B / 128);
    gemm_kernel<<<grid, 256>>>(xembs, yembs, N);

    topk_loss_kernel<<<B, 256>>>(target, numneg, out, N, B);
}

// round 3
// speedup vs baseline: 2.4030x; 2.4030x over previous
#include <cuda_runtime.h>
#include <cuda_bf16.h>
#include <cstdint>

// ---------------------------------------------------------------------------
// Problem constants
// ---------------------------------------------------------------------------
#define DIM   128
#define B_FIX 256
#define N_FIX 131072
#define TN    64                  // y-rows per subtile
#define SUBT  (N_FIX / TN)        // 2048
#define GRIDX 148
#define KK    8
#define NSLOT (GRIDX * 2)         // per-row candidate slots (CTA x n-group)
#define NC    (NSLOT * KK)        // 2368 candidates per row
#define CAND_SLACK 16
#define NEGF  -3.0e38f

// ---------------------------------------------------------------------------
// Global scratch (static)
// ---------------------------------------------------------------------------
__device__ float g_cval[(size_t)B_FIX * NC];
__device__ int   g_cidx[(size_t)B_FIX * NC];
__device__ int   g_pos[B_FIX];

// SMEM layout (bytes)
#define XS_OFF   0
#define XS_SIZE  (256 * 256)                 // 256 rows x 256B (bf16 swizzled)
#define YS_OFF   XS_SIZE                     // 65536
#define YS_SIZE  (64 * 256)                  // 16384 per buffer
#define STG_OFF  (YS_OFF + 2 * YS_SIZE)      // 98304
#define STG_WARP 2112                        // 527 words rounded up
#define SMEM_TOTAL (STG_OFF + 8 * STG_WARP)  // 115200

// ---------------------------------------------------------------------------
// PTX helpers (baseline ISA only — no 'a' features)
// ---------------------------------------------------------------------------
__device__ __forceinline__ uint32_t smem_u32(const void* p) {
    uint32_t a;
    asm("{ .reg .u64 t; cvta.to.shared.u64 t, %1; cvt.u32.u64 %0, t; }"
        : "=r"(a) : "l"(p));
    return a;
}

__device__ __forceinline__ void ldsm_x4(uint32_t* r, uint32_t addr) {
    asm volatile("ldmatrix.sync.aligned.m8n8.x4.shared.b16 {%0,%1,%2,%3}, [%4];"
                 : "=r"(r[0]), "=r"(r[1]), "=r"(r[2]), "=r"(r[3]) : "r"(addr));
}

__device__ __forceinline__ void mma_bf16(float* d, const uint32_t* a,
                                         uint32_t b0, uint32_t b1) {
    asm volatile(
        "mma.sync.aligned.m16n8k16.row.col.f32.bf16.bf16.f32 "
        "{%0,%1,%2,%3}, {%4,%5,%6,%7}, {%8,%9}, {%0,%1,%2,%3};"
        : "+f"(d[0]), "+f"(d[1]), "+f"(d[2]), "+f"(d[3])
        : "r"(a[0]), "r"(a[1]), "r"(a[2]), "r"(a[3]), "r"(b0), "r"(b1));
}

__device__ __forceinline__ void topk_insert(float* tv, int* ti, float v, int idx) {
    if (v > tv[KK - 1]) {
        tv[KK - 1] = v; ti[KK - 1] = idx;
#pragma unroll
        for (int j = KK - 1; j > 0; j--) {
            if (tv[j] > tv[j - 1]) {
                float a = tv[j]; tv[j] = tv[j - 1]; tv[j - 1] = a;
                int   b = ti[j]; ti[j] = ti[j - 1]; ti[j - 1] = b;
            }
        }
    }
}

// ---------------------------------------------------------------------------
// Kernel 0: zero output + decode pos_inds (dtype sniff: int64 vs int32)
// ---------------------------------------------------------------------------
__global__ void prep_kernel(const void* __restrict__ pos_inds, float* out,
                            int N, int B) {
    int t = threadIdx.x;
    if (t == 0) out[0] = 0.0f;
    __shared__ int s_not64;
    if (t == 0) s_not64 = 0;
    __syncthreads();
    const long long* q = (const long long*)pos_inds;
    if (t < B / 2) {
        long long v = q[t];
        if (v < 0 || v >= (long long)N) atomicExch(&s_not64, 1);
    }
    __syncthreads();
    if (t < B) {
        if (s_not64) g_pos[t] = ((const int*)pos_inds)[t];
        else         g_pos[t] = (int)q[t];
    }
}

// ---------------------------------------------------------------------------
// Kernel 1: persistent bf16 mma.sync GEMM + fused per-row top-8 mining.
//   256 threads = 8 warps = 4 m-groups x 2 n-groups.
//   Warp tile: 32 (M) x 32 (N); two M-halves cover all 256 x-rows.
// ---------------------------------------------------------------------------
__global__ __launch_bounds__(256, 1)
void gemm_topk_kernel(const float* __restrict__ X, const float* __restrict__ Y) {
    extern __shared__ char smem[];
    const uint32_t sb = smem_u32(smem);
    const int t    = threadIdx.x;
    const int lane = t & 31;
    const int wid  = t >> 5;
    const int wm   = wid >> 1;    // 0..3 (m-group)
    const int ng   = wid & 1;     // 0..1 (n-group)
    const int bx   = blockIdx.x;

    // --- load X (256x128 fp32 -> bf16) into swizzled SMEM ---
    {
        const float4* xs = (const float4*)X;
#pragma unroll
        for (int i = 0; i < 32; i++) {
            int fi = t + i * 256;
            int row = fi >> 5, c4 = fi & 31;
            float4 v = xs[fi];
            __nv_bfloat162 p0 = __float22bfloat162_rn(make_float2(v.x, v.y));
            __nv_bfloat162 p1 = __float22bfloat162_rn(make_float2(v.z, v.w));
            uint32_t off = XS_OFF + row * 256 +
                           (((c4 >> 1) ^ (row & 7)) << 4) + ((c4 & 1) << 3);
            *reinterpret_cast<uint2*>(smem + off) =
                make_uint2(*reinterpret_cast<uint32_t*>(&p0),
                           *reinterpret_cast<uint32_t*>(&p1));
        }
    }

    // --- prefetch + store first Y subtile into buffer 0 ---
    float4 pf[8];
    {
        const float4* ys = (const float4*)(Y + (size_t)bx * TN * DIM);
#pragma unroll
        for (int i = 0; i < 8; i++) pf[i] = ys[t + i * 256];
#pragma unroll
        for (int i = 0; i < 8; i++) {
            int fi = t + i * 256;
            int row = fi >> 5, c4 = fi & 31;
            __nv_bfloat162 p0 = __float22bfloat162_rn(make_float2(pf[i].x, pf[i].y));
            __nv_bfloat162 p1 = __float22bfloat162_rn(make_float2(pf[i].z, pf[i].w));
            uint32_t off = YS_OFF + row * 256 +
                           (((c4 >> 1) ^ (row & 7)) << 4) + ((c4 & 1) << 3);
            *reinterpret_cast<uint2*>(smem + off) =
                make_uint2(*reinterpret_cast<uint32_t*>(&p0),
                           *reinterpret_cast<uint32_t*>(&p1));
        }
    }
    __syncthreads();

    // --- per-lane top-8 lists: one row per M-half ---
    float tv[2][KK];
    int   ti[2][KK];
#pragma unroll
    for (int h = 0; h < 2; h++)
#pragma unroll
        for (int j = 0; j < KK; j++) { tv[h][j] = NEGF; ti[h][j] = -1; }

    uint32_t* stg = reinterpret_cast<uint32_t*>(smem + STG_OFF + wid * STG_WARP);

    int cb = 0;
    for (int st = bx; st < SUBT; st += GRIDX) {
        const int stn = st + GRIDX;
        const bool has_next = (stn < SUBT);

        // issue next-subtile LDGs early (overlap with compute)
        if (has_next) {
            const float4* ys = (const float4*)(Y + (size_t)stn * TN * DIM);
#pragma unroll
            for (int i = 0; i < 8; i++) pf[i] = ys[t + i * 256];
        }

        const uint32_t ysb = sb + YS_OFF + cb * YS_SIZE;

#pragma unroll
        for (int h = 0; h < 2; h++) {
            const int m0 = h * 128 + wm * 32;
            float acc[2][4][4];
#pragma unroll
            for (int mt = 0; mt < 2; mt++)
#pragma unroll
                for (int nt = 0; nt < 4; nt++)
#pragma unroll
                    for (int e = 0; e < 4; e++) acc[mt][nt][e] = 0.0f;

            const int sub = lane >> 3, lr = lane & 7;
#pragma unroll
            for (int kt = 0; kt < 8; kt++) {
                uint32_t a[2][4], b[2][4];
                // A fragments (two m16 tiles)
                {
                    int rowa = m0 + ((sub & 1) << 3) + lr;
                    int ca   = 2 * kt + (sub >> 1);
#pragma unroll
                    for (int mt = 0; mt < 2; mt++) {
                        int row = rowa + mt * 16;
                        uint32_t addr = sb + XS_OFF + row * 256 +
                                        ((ca ^ (row & 7)) << 4);
                        ldsm_x4(a[mt], addr);
                    }
                }
                // B fragments (four n8 tiles via two x4 loads)
                {
                    int rowb = ng * 32 + ((sub >> 1) << 3) + lr;
                    int cbk  = 2 * kt + (sub & 1);
#pragma unroll
                    for (int p = 0; p < 2; p++) {
                        int row = rowb + p * 16;
                        uint32_t addr = ysb + row * 256 + ((cbk ^ (row & 7)) << 4);
                        ldsm_x4(b[p], addr);
                    }
                }
#pragma unroll
                for (int mt = 0; mt < 2; mt++)
#pragma unroll
                    for (int nt = 0; nt < 4; nt++)
                        mma_bf16(acc[mt][nt], a[mt],
                                 b[nt >> 1][(nt & 1) * 2],
                                 b[nt >> 1][(nt & 1) * 2 + 1]);
            }

            // --- stage warp tile to SMEM (bf16, stride-33 words) ---
            __syncwarp();
            const int g = lane >> 2, tg = lane & 3;
#pragma unroll
            for (int mt = 0; mt < 2; mt++)
#pragma unroll
                for (int nt = 0; nt < 4; nt++) {
                    int cp = nt * 4 + tg;
                    __nv_bfloat162 lo = __float22bfloat162_rn(
                        make_float2(acc[mt][nt][0], acc[mt][nt][1]));
                    __nv_bfloat162 hi = __float22bfloat162_rn(
                        make_float2(acc[mt][nt][2], acc[mt][nt][3]));
                    stg[cp * 33 + mt * 16 + g]     = *reinterpret_cast<uint32_t*>(&lo);
                    stg[cp * 33 + mt * 16 + g + 8] = *reinterpret_cast<uint32_t*>(&hi);
                }
            __syncwarp();

            // --- scan own row (local row = lane), update top-8 ---
            const int colbase = st * TN + ng * 32;
#pragma unroll
            for (int cp = 0; cp < 16; cp++) {
                uint32_t w = stg[cp * 33 + lane];
                __nv_bfloat162 v2 = *reinterpret_cast<__nv_bfloat162*>(&w);
                topk_insert(tv[h], ti[h], __bfloat162float(v2.x), colbase + cp * 2);
                topk_insert(tv[h], ti[h], __bfloat162float(v2.y), colbase + cp * 2 + 1);
            }
            __syncwarp();
        }

        // --- convert + store prefetched Y into the other buffer ---
        if (has_next) {
            char* yd = smem + YS_OFF + (cb ^ 1) * YS_SIZE;
#pragma unroll
            for (int i = 0; i < 8; i++) {
                int fi = t + i * 256;
                int row = fi >> 5, c4 = fi & 31;
                __nv_bfloat162 p0 = __float22bfloat162_rn(make_float2(pf[i].x, pf[i].y));
                __nv_bfloat162 p1 = __float22bfloat162_rn(make_float2(pf[i].z, pf[i].w));
                uint32_t off = (uint32_t)(row * 256) +
                               (((c4 >> 1) ^ (row & 7)) << 4) + ((c4 & 1) << 3);
                *reinterpret_cast<uint2*>(yd + off) =
                    make_uint2(*reinterpret_cast<uint32_t*>(&p0),
                               *reinterpret_cast<uint32_t*>(&p1));
            }
        }
        cb ^= 1;
        __syncthreads();
    }

    // --- write per-(row, CTA, n-group) candidates ---
#pragma unroll
    for (int h = 0; h < 2; h++) {
        int row = h * 128 + wm * 32 + lane;
        size_t base = (size_t)row * NC + (size_t)(bx * 2 + ng) * KK;
#pragma unroll
        for (int j = 0; j < KK; j++) {
            g_cval[base + j] = tv[h][j];
            g_cidx[base + j] = ti[h][j];
        }
    }
}

// ---------------------------------------------------------------------------
// Kernel 2: merge candidates -> top-16 (excl. pos) -> exact fp32 rescore ->
//           hinge + masked softmax -> atomicAdd mean contribution
// ---------------------------------------------------------------------------
__global__ __launch_bounds__(128) void merge_loss_kernel(
    const float* __restrict__ X, const float* __restrict__ Y,
    const int* __restrict__ numneg_ptr, float* __restrict__ out,
    int N, int Btot)
{
    const int b = blockIdx.x;
    const int t = threadIdx.x;

    int num_neg = 5;
    if (numneg_ptr) {
        int nn = *numneg_ptr;
        if (nn >= 1 && nn <= KK) num_neg = nn;
    }
    const int pos = g_pos[b];

    __shared__ float sval[NC];
    __shared__ int   sidx[NC];
    __shared__ float rv[128];
    __shared__ int   ri[128];
    __shared__ int   topi[CAND_SLACK];
    __shared__ float xrow[DIM];
    __shared__ float ex[CAND_SLACK + 1];

    const size_t cbase = (size_t)b * NC;
    for (int j = t; j < NC; j += 128) {
        int   id = g_cidx[cbase + j];
        float v  = g_cval[cbase + j];
        if (id == pos || id < 0) v = NEGF;
        sval[j] = v;
        sidx[j] = id;
    }
    if (t < DIM) xrow[t] = X[(size_t)b * DIM + t];
    __syncthreads();

    for (int r = 0; r < CAND_SLACK; r++) {
        float bv = NEGF; int bj = -1;
        for (int j = t; j < NC; j += 128)
            if (sval[j] > bv) { bv = sval[j]; bj = j; }
        rv[t] = bv; ri[t] = bj;
        __syncthreads();
        for (int s = 64; s > 0; s >>= 1) {
            if (t < s && rv[t + s] > rv[t]) { rv[t] = rv[t + s]; ri[t] = ri[t + s]; }
            __syncthreads();
        }
        if (t == 0) {
            int j = ri[0];
            topi[r] = (j >= 0) ? sidx[j] : -1;
            if (j >= 0) sval[j] = NEGF;
        }
        __syncthreads();
    }

    // exact fp32 rescore of 16 candidates + sim_p
    if (t < CAND_SLACK + 1) {
        int idx = (t < CAND_SLACK) ? topi[t] : pos;
        bool valid = (idx >= 0 && idx < N);
        int safe = valid ? idx : 0;
        const float* yr = Y + (size_t)safe * DIM;
        float d = 0.0f;
#pragma unroll 8
        for (int k = 0; k < DIM; k++) d = fmaf(xrow[k], yr[k], d);
        ex[t] = valid ? d : NEGF;
    }
    __syncthreads();

    if (t == 0) {
        float a[CAND_SLACK];
#pragma unroll
        for (int j = 0; j < CAND_SLACK; j++) a[j] = ex[j];
#pragma unroll
        for (int i = 1; i < CAND_SLACK; i++) {
            float key = a[i];
            int j = i - 1;
            while (j >= 0 && a[j] < key) { a[j + 1] = a[j]; j--; }
            a[j + 1] = key;
        }
        float sim_p = ex[CAND_SLACK];
        float loss[KK], m[KK], mx = NEGF;
        for (int r = 0; r < num_neg; r++) {
            float sn = a[r];
            float l = sn - sim_p + 0.3f;
            l = (l > 0.0f) ? l : 0.0f;
            float mm = (l != 0.0f) ? sn : 0.0f;
            loss[r] = l; m[r] = mm;
            if (mm > mx) mx = mm;
        }
        float ssum = 0.0f, res = 0.0f;
        float e[KK];
        for (int r = 0; r < num_neg; r++) { e[r] = expf(m[r] - mx); ssum += e[r]; }
        for (int r = 0; r < num_neg; r++) res += loss[r] * e[r];
        res /= ssum;
        atomicAdd(out, res / ((float)Btot * (float)num_neg));
    }
}

// ---------------------------------------------------------------------------
// kernel_launch
// ---------------------------------------------------------------------------
extern "C" void kernel_launch(void* const* d_in, const int* in_sizes, int n_in,
                              void* d_out, int out_size)
{
    const float* xembs  = (const float*)d_in[0];
    const float* yembs  = (const float*)d_in[1];
    const void*  posind = d_in[3];
    const int*   numneg = (n_in >= 5) ? (const int*)d_in[4] : nullptr;

    const int B = in_sizes[0] / DIM;   // 256
    const int N = in_sizes[1] / DIM;   // 131072
    float* out = (float*)d_out;

    prep_kernel<<<1, 256>>>(posind, out, N, B);

    static int smem_set = 0;
    if (!smem_set) {
        cudaFuncSetAttribute(gemm_topk_kernel,
                             cudaFuncAttributeMaxDynamicSharedMemorySize,
                             SMEM_TOTAL);
        smem_set = 1;
    }
    gemm_topk_kernel<<<GRIDX, 256, SMEM_TOTAL>>>(xembs, yembs);

    merge_loss_kernel<<<B, 128>>>(xembs, yembs, numneg, out, N, B);
}

// round 4
// speedup vs baseline: 7.8064x; 3.2486x over previous
#include <cuda_runtime.h>
#include <cuda_bf16.h>
#include <cstdint>

// ---------------------------------------------------------------------------
// Problem constants
// ---------------------------------------------------------------------------
#define DIM   128
#define B_FIX 256
#define N_FIX 131072
#define TN    64                  // y-rows per subtile
#define SUBT  (N_FIX / TN)        // 2048
#define GRIDX 148
#define NC    (GRIDX * 2 * 4 * 4) // 4736 packed candidates per row
#define NG    15                  // groups rescored exactly (8 elems each)
#define KK    8
#define NEGF  -3.0e38f

// ---------------------------------------------------------------------------
// Global scratch (static)
// ---------------------------------------------------------------------------
__device__ uint32_t g_cpack[(size_t)B_FIX * NC];   // key16<<16 | group14
__device__ int      g_pos[B_FIX];

// SMEM layout for gemm kernel (bytes)
#define XS_OFF   0
#define XS_SIZE  (256 * 256)                 // 256 rows x 256B (bf16 swizzled)
#define YS_OFF   XS_SIZE                     // 65536
#define YS_SIZE  (64 * 256)                  // 16384 per buffer
#define SMEM_TOTAL (YS_OFF + 2 * YS_SIZE)    // 98304

// ---------------------------------------------------------------------------
// Helpers
// ---------------------------------------------------------------------------
__device__ __forceinline__ uint32_t smem_u32(const void* p) {
    uint32_t a;
    asm("{ .reg .u64 t; cvta.to.shared.u64 t, %1; cvt.u32.u64 %0, t; }"
        : "=r"(a) : "l"(p));
    return a;
}

__device__ __forceinline__ void ldsm_x4(uint32_t* r, uint32_t addr) {
    asm volatile("ldmatrix.sync.aligned.m8n8.x4.shared.b16 {%0,%1,%2,%3}, [%4];"
                 : "=r"(r[0]), "=r"(r[1]), "=r"(r[2]), "=r"(r[3]) : "r"(addr));
}

__device__ __forceinline__ void mma_bf16(float* d, const uint32_t* a,
                                         uint32_t b0, uint32_t b1) {
    asm volatile(
        "mma.sync.aligned.m16n8k16.row.col.f32.bf16.bf16.f32 "
        "{%0,%1,%2,%3}, {%4,%5,%6,%7}, {%8,%9}, {%0,%1,%2,%3};"
        : "+f"(d[0]), "+f"(d[1]), "+f"(d[2]), "+f"(d[3])
        : "r"(a[0]), "r"(a[1]), "r"(a[2]), "r"(a[3]), "r"(b0), "r"(b1));
}

// monotone uint key from float bits (order-preserving, both signs)
__device__ __forceinline__ uint32_t fkey(float v) {
    uint32_t f = __float_as_uint(v);
    return f ^ (uint32_t)(((int32_t)f >> 31) | 0x80000000);
}

// branchless sorted-descending insert chains (IMNMX only)
__device__ __forceinline__ void chain4(uint32_t* L, uint32_t m) {
#pragma unroll
    for (int j = 0; j < 4; j++) {
        uint32_t mx = max(L[j], m);
        m = min(L[j], m);
        L[j] = mx;
    }
}
__device__ __forceinline__ void chain8(uint32_t* L, uint32_t m) {
#pragma unroll
    for (int j = 0; j < 8; j++) {
        uint32_t mx = max(L[j], m);
        m = min(L[j], m);
        L[j] = mx;
    }
}

// ---------------------------------------------------------------------------
// Kernel 1: persistent bf16 mma.sync GEMM + in-register group-max mining.
//   256 threads = 8 warps = 4 m-groups x 2 n-groups; warp tile 32(M) x 32(N),
//   two M-halves cover 256 x-rows. Block 0 additionally does prep work.
// ---------------------------------------------------------------------------
__global__ __launch_bounds__(256, 1)
void gemm_topk_kernel(const float* __restrict__ X, const float* __restrict__ Y,
                      const void* __restrict__ pos_inds, float* __restrict__ outp,
                      int N, int B) {
    extern __shared__ char smem[];
    __shared__ int s_not64;
    const uint32_t sb = smem_u32(smem);
    const int t    = threadIdx.x;
    const int lane = t & 31;
    const int wid  = t >> 5;
    const int wm   = wid >> 1;    // m-group 0..3
    const int ng   = wid & 1;     // n-group 0..1
    const int g    = lane >> 2;   // fragment row-within-8
    const int tg   = lane & 3;    // fragment col-pair
    const int bx   = blockIdx.x;

    // --- prep (block 0): zero out, sniff pos_inds dtype ---
    if (bx == 0 && t == 0) { outp[0] = 0.0f; s_not64 = 0; }
    __syncthreads();
    if (bx == 0 && t < B / 2) {
        long long v = ((const long long*)pos_inds)[t];
        if (v < 0 || v >= (long long)N) atomicExch(&s_not64, 1);
    }

    // --- load X (256x128 fp32 -> bf16) into swizzled SMEM ---
    {
        const float4* xs = (const float4*)X;
#pragma unroll
        for (int i = 0; i < 32; i++) {
            int fi = t + i * 256;
            int row = fi >> 5, c4 = fi & 31;
            float4 v = xs[fi];
            __nv_bfloat162 p0 = __float22bfloat162_rn(make_float2(v.x, v.y));
            __nv_bfloat162 p1 = __float22bfloat162_rn(make_float2(v.z, v.w));
            uint32_t off = XS_OFF + row * 256 +
                           (((c4 >> 1) ^ (row & 7)) << 4) + ((c4 & 1) << 3);
            *reinterpret_cast<uint2*>(smem + off) =
                make_uint2(*reinterpret_cast<uint32_t*>(&p0),
                           *reinterpret_cast<uint32_t*>(&p1));
        }
    }

    // --- prefetch + store first Y subtile into buffer 0 ---
    float4 pf[8];
    {
        const float4* ys = (const float4*)(Y + (size_t)bx * TN * DIM);
#pragma unroll
        for (int i = 0; i < 8; i++) pf[i] = ys[t + i * 256];
#pragma unroll
        for (int i = 0; i < 8; i++) {
            int fi = t + i * 256;
            int row = fi >> 5, c4 = fi & 31;
            __nv_bfloat162 p0 = __float22bfloat162_rn(make_float2(pf[i].x, pf[i].y));
            __nv_bfloat162 p1 = __float22bfloat162_rn(make_float2(pf[i].z, pf[i].w));
            uint32_t off = YS_OFF + row * 256 +
                           (((c4 >> 1) ^ (row & 7)) << 4) + ((c4 & 1) << 3);
            *reinterpret_cast<uint2*>(smem + off) =
                make_uint2(*reinterpret_cast<uint32_t*>(&p0),
                           *reinterpret_cast<uint32_t*>(&p1));
        }
    }
    __syncthreads();

    if (bx == 0 && t < B) {
        g_pos[t] = s_not64 ? ((const int*)pos_inds)[t]
                           : (int)((const long long*)pos_inds)[t];
    }

    // --- per-lane candidate lists: 8 rows (h,mt,rh), top-4 packed keys each ---
    uint32_t L[2][2][2][4];
#pragma unroll
    for (int h = 0; h < 2; h++)
#pragma unroll
        for (int mt = 0; mt < 2; mt++)
#pragma unroll
            for (int rh = 0; rh < 2; rh++)
#pragma unroll
                for (int j = 0; j < 4; j++) L[h][mt][rh][j] = 0;

    const int sub = lane >> 3, lr = lane & 7;
    int cb = 0;
    int it = 0;
    for (int st = bx; st < SUBT; st += GRIDX, it++) {
        const int stn = st + GRIDX;
        const bool has_next = (stn < SUBT);

        if (has_next) {
            const float4* ys = (const float4*)(Y + (size_t)stn * TN * DIM);
#pragma unroll
            for (int i = 0; i < 8; i++) pf[i] = ys[t + i * 256];
        }

        const uint32_t ysb = sb + YS_OFF + cb * YS_SIZE;

#pragma unroll
        for (int h = 0; h < 2; h++) {
            const int m0 = h * 128 + wm * 32;
            float acc[2][4][4];
#pragma unroll
            for (int mt = 0; mt < 2; mt++)
#pragma unroll
                for (int nt = 0; nt < 4; nt++)
#pragma unroll
                    for (int e = 0; e < 4; e++) acc[mt][nt][e] = 0.0f;

#pragma unroll
            for (int kt = 0; kt < 8; kt++) {
                uint32_t a[2][4], b[2][4];
                {
                    int rowa = m0 + ((sub & 1) << 3) + lr;
                    int ca   = 2 * kt + (sub >> 1);
#pragma unroll
                    for (int mt = 0; mt < 2; mt++) {
                        int row = rowa + mt * 16;
                        uint32_t addr = sb + XS_OFF + row * 256 +
                                        ((ca ^ (row & 7)) << 4);
                        ldsm_x4(a[mt], addr);
                    }
                }
                {
                    int rowb = ng * 32 + ((sub >> 1) << 3) + lr;
                    int cbk  = 2 * kt + (sub & 1);
#pragma unroll
                    for (int p = 0; p < 2; p++) {
                        int row = rowb + p * 16;
                        uint32_t addr = ysb + row * 256 + ((cbk ^ (row & 7)) << 4);
                        ldsm_x4(b[p], addr);
                    }
                }
#pragma unroll
                for (int mt = 0; mt < 2; mt++)
#pragma unroll
                    for (int nt = 0; nt < 4; nt++)
                        mma_bf16(acc[mt][nt], a[mt],
                                 b[nt >> 1][(nt & 1) * 2],
                                 b[nt >> 1][(nt & 1) * 2 + 1]);
            }

            // --- in-register scan: one group-max insert per (mt, rh) ---
#pragma unroll
            for (int mt = 0; mt < 2; mt++)
#pragma unroll
                for (int rh = 0; rh < 2; rh++) {
                    float v = fmaxf(
                        fmaxf(fmaxf(acc[mt][0][rh*2], acc[mt][0][rh*2+1]),
                              fmaxf(acc[mt][1][rh*2], acc[mt][1][rh*2+1])),
                        fmaxf(fmaxf(acc[mt][2][rh*2], acc[mt][2][rh*2+1]),
                              fmaxf(acc[mt][3][rh*2], acc[mt][3][rh*2+1])));
                    uint32_t pk = (fkey(v) & 0xFFFF0000u) | (uint32_t)it;
                    chain4(L[h][mt][rh], pk);
                }
        }

        if (has_next) {
            char* yd = smem + YS_OFF + (cb ^ 1) * YS_SIZE;
#pragma unroll
            for (int i = 0; i < 8; i++) {
                int fi = t + i * 256;
                int row = fi >> 5, c4 = fi & 31;
                __nv_bfloat162 p0 = __float22bfloat162_rn(make_float2(pf[i].x, pf[i].y));
                __nv_bfloat162 p1 = __float22bfloat162_rn(make_float2(pf[i].z, pf[i].w));
                uint32_t off = (uint32_t)(row * 256) +
                               (((c4 >> 1) ^ (row & 7)) << 4) + ((c4 & 1) << 3);
                *reinterpret_cast<uint2*>(yd + off) =
                    make_uint2(*reinterpret_cast<uint32_t*>(&p0),
                               *reinterpret_cast<uint32_t*>(&p1));
            }
        }
        cb ^= 1;
        __syncthreads();
    }

    // --- writeout: key16<<16 | group (group = st*8 + ng*4 + tg, 14 bits) ---
#pragma unroll
    for (int h = 0; h < 2; h++)
#pragma unroll
        for (int mt = 0; mt < 2; mt++)
#pragma unroll
            for (int rh = 0; rh < 2; rh++) {
                int row = h * 128 + wm * 32 + mt * 16 + rh * 8 + g;
                size_t base = (size_t)row * NC +
                              (size_t)((bx * 2 + ng) * 4 + tg) * 4;
#pragma unroll
                for (int j = 0; j < 4; j++) {
                    uint32_t pk = L[h][mt][rh][j];
                    uint32_t keyhi = pk & 0xFFFF0000u;
                    uint32_t o = 0;
                    if (keyhi) {
                        int itv = (int)(pk & 0xFFFFu);
                        o = keyhi |
                            (uint32_t)((bx + itv * GRIDX) * 8 + ng * 4 + tg);
                    }
                    g_cpack[base + j] = o;
                }
            }
}

// ---------------------------------------------------------------------------
// Kernel 2: per-row merge -> top-NG groups -> exact fp32 rescore (120 elems +
//           pos) -> exact top-num_neg -> hinge + masked softmax -> atomicAdd
// ---------------------------------------------------------------------------
__global__ __launch_bounds__(128) void merge_loss_kernel(
    const float* __restrict__ X, const float* __restrict__ Y,
    const int* __restrict__ numneg_ptr, float* __restrict__ out,
    int N, int Btot)
{
    const int b = blockIdx.x;
    const int t = threadIdx.x;

    __shared__ float    xrow[DIM];
    __shared__ uint32_t cand[1024];
    __shared__ uint32_t wtop[NG];
    __shared__ float    ex[121];
    __shared__ float    stop[KK];

    int num_neg = 5;
    if (numneg_ptr) {
        int nn = *numneg_ptr;
        if (nn >= 1 && nn <= KK) num_neg = nn;
    }
    const int pos = g_pos[b];

    xrow[t] = X[(size_t)b * DIM + t];

    // stage 1: per-thread top-8 packed candidates over strided subset
    {
        const uint32_t* cp = g_cpack + (size_t)b * NC;
        uint32_t M[8];
#pragma unroll
        for (int j = 0; j < 8; j++) M[j] = 0;
        for (int j = t; j < NC; j += 128) chain8(M, cp[j]);
#pragma unroll
        for (int j = 0; j < 8; j++) cand[t * 8 + j] = M[j];
    }
    __syncthreads();

    // stage 2: warp 0 selects global top-NG groups from 1024 survivors
    if (t < 32) {
        uint32_t W[8];
#pragma unroll
        for (int j = 0; j < 8; j++) W[j] = 0;
        for (int k = 0; k < 32; k++) chain8(W, cand[t + (k << 5)]);
        int p = 0;
        for (int r = 0; r < NG; r++) {
            uint32_t head = (p < 8) ? W[p] : 0u;
            uint32_t w = head;
#pragma unroll
            for (int off = 16; off; off >>= 1) {
                uint32_t o = __shfl_xor_sync(0xFFFFFFFFu, w, off);
                w = (o > w) ? o : w;
            }
            if (head == w && w != 0u && p < 8) p++;
            if (t == 0) wtop[r] = w;
        }
    }
    __syncthreads();

    // rescore: NG groups x 8 elements + pos = 121 exact fp32 dots
    {
        int col = -1;
        if (t < NG * 8) {
            uint32_t w = wtop[t >> 3];
            if (w > 0xFFFFu) {
                int grp = (int)(w & 0xFFFFu);
                int stv = grp >> 3, ngv = (grp >> 2) & 1, tgv = grp & 3;
                int e = t & 7;
                col = stv * 64 + ngv * 32 + ((e >> 1) << 3) + tgv * 2 + (e & 1);
                if (col == pos) col = -1;
            }
        } else if (t == NG * 8) {
            col = pos;
        }
        if (t <= NG * 8) {
            float d = NEGF;
            if (col >= 0 && col < N) {
                const float4* yr = (const float4*)(Y + (size_t)col * DIM);
                const float4* xr = (const float4*)xrow;
                d = 0.0f;
#pragma unroll
                for (int k = 0; k < 32; k++) {
                    float4 yv = yr[k], xv = xr[k];
                    d = fmaf(xv.x, yv.x, d);
                    d = fmaf(xv.y, yv.y, d);
                    d = fmaf(xv.z, yv.z, d);
                    d = fmaf(xv.w, yv.w, d);
                }
            }
            ex[t] = d;
        }
    }
    __syncthreads();

    // exact top-8 of ex[0..119] via warp 0 (float compare, idx tie-break)
    if (t < 32) {
        float v[4];
        int   id[4];
#pragma unroll
        for (int j = 0; j < 4; j++) {
            int p2 = t * 4 + j;
            v[j]  = (p2 < NG * 8) ? ex[p2] : NEGF;
            id[j] = p2;
        }
        // sort 4 descending (value, then idx asc)
#pragma unroll
        for (int a = 0; a < 4; a++)
#pragma unroll
            for (int c = a + 1; c < 4; c++)
                if (v[c] > v[a] || (v[c] == v[a] && id[c] < id[a])) {
                    float tv = v[a]; v[a] = v[c]; v[c] = tv;
                    int   ti = id[a]; id[a] = id[c]; id[c] = ti;
                }
        int p = 0;
        for (int r = 0; r < KK; r++) {
            float hv = (p < 4) ? v[p] : NEGF;
            int   hi = (p < 4) ? id[p] : 1000 + t;
            float wv = hv; int wi = hi;
#pragma unroll
            for (int off = 16; off; off >>= 1) {
                float ov = __shfl_xor_sync(0xFFFFFFFFu, wv, off);
                int   oi = __shfl_xor_sync(0xFFFFFFFFu, wi, off);
                if (ov > wv || (ov == wv && oi < wi)) { wv = ov; wi = oi; }
            }
            if (hi == wi && p < 4) p++;
            if (t == 0) stop[r] = wv;
        }
    }
    __syncthreads();

    if (t == 0) {
        float sim_p = ex[NG * 8];
        float loss[KK], m[KK], mx = NEGF;
        for (int r = 0; r < num_neg; r++) {
            float sn = stop[r];
            float l = sn - sim_p + 0.3f;
            l = (l > 0.0f) ? l : 0.0f;
            float mm = (l != 0.0f) ? sn : 0.0f;
            loss[r] = l; m[r] = mm;
            if (mm > mx) mx = mm;
        }
        float ssum = 0.0f, res = 0.0f;
        float e[KK];
        for (int r = 0; r < num_neg; r++) { e[r] = expf(m[r] - mx); ssum += e[r]; }
        for (int r = 0; r < num_neg; r++) res += loss[r] * e[r];
        res /= ssum;
        atomicAdd(out, res / ((float)Btot * (float)num_neg));
    }
}

// ---------------------------------------------------------------------------
// kernel_launch
// ---------------------------------------------------------------------------
extern "C" void kernel_launch(void* const* d_in, const int* in_sizes, int n_in,
                              void* d_out, int out_size)
{
    const float* xembs  = (const float*)d_in[0];
    const float* yembs  = (const float*)d_in[1];
    const void*  posind = d_in[3];
    const int*   numneg = (n_in >= 5) ? (const int*)d_in[4] : nullptr;

    const int B = in_sizes[0] / DIM;   // 256
    const int N = in_sizes[1] / DIM;   // 131072
    float* out = (float*)d_out;

    static int smem_set = 0;
    if (!smem_set) {
        cudaFuncSetAttribute(gemm_topk_kernel,
                             cudaFuncAttributeMaxDynamicSharedMemorySize,
                             SMEM_TOTAL);
        smem_set = 1;
    }
    gemm_topk_kernel<<<GRIDX, 256, SMEM_TOTAL>>>(xembs, yembs, posind, out, N, B);
    merge_loss_kernel<<<B, 128>>>(xembs, yembs, numneg, out, N, B);
}

// round 5
// speedup vs baseline: 8.3236x; 1.0663x over previous
#include <cuda_runtime.h>
#include <cuda_bf16.h>
#include <cstdint>

// ---------------------------------------------------------------------------
// Problem constants
// ---------------------------------------------------------------------------
#define DIM   128
#define B_FIX 256
#define N_FIX 131072
#define TN    64                  // y-rows per subtile
#define SUBT  (N_FIX / TN)        // 2048
#define GRIDX 148
#define NC    (GRIDX * 2 * 4)     // 1184 packed candidates per row
#define NG    15                  // groups rescored exactly (8 elems each)
#define KK    8
#define NEGF  -3.0e38f

// ---------------------------------------------------------------------------
// Global scratch (static)
// ---------------------------------------------------------------------------
__device__ uint32_t g_cpack[(size_t)B_FIX * NC];   // key16<<16 | group14
__device__ int      g_pos[B_FIX];

// SMEM layout for gemm kernel (bytes)
#define XS_OFF   0
#define XS_SIZE  (256 * 256)                 // 256 rows x 256B (bf16 swizzled)
#define YS_OFF   XS_SIZE                     // 65536
#define YS_SIZE  (64 * 256)                  // 16384 per buffer
#define SMEM_TOTAL (YS_OFF + 2 * YS_SIZE)    // 98304

// ---------------------------------------------------------------------------
// Helpers
// ---------------------------------------------------------------------------
__device__ __forceinline__ uint32_t smem_u32(const void* p) {
    uint32_t a;
    asm("{ .reg .u64 t; cvta.to.shared.u64 t, %1; cvt.u32.u64 %0, t; }"
        : "=r"(a) : "l"(p));
    return a;
}

__device__ __forceinline__ void ldsm_x4(uint32_t* r, uint32_t addr) {
    asm volatile("ldmatrix.sync.aligned.m8n8.x4.shared.b16 {%0,%1,%2,%3}, [%4];"
                 : "=r"(r[0]), "=r"(r[1]), "=r"(r[2]), "=r"(r[3]) : "r"(addr));
}

__device__ __forceinline__ void mma_bf16(float* d, const uint32_t* a,
                                         uint32_t b0, uint32_t b1) {
    asm volatile(
        "mma.sync.aligned.m16n8k16.row.col.f32.bf16.bf16.f32 "
        "{%0,%1,%2,%3}, {%4,%5,%6,%7}, {%8,%9}, {%0,%1,%2,%3};"
        : "+f"(d[0]), "+f"(d[1]), "+f"(d[2]), "+f"(d[3])
        : "r"(a[0]), "r"(a[1]), "r"(a[2]), "r"(a[3]), "r"(b0), "r"(b1));
}

// monotone uint key from float bits (order-preserving, both signs)
__device__ __forceinline__ uint32_t fkey(float v) {
    uint32_t f = __float_as_uint(v);
    return f ^ (uint32_t)(((int32_t)f >> 31) | 0x80000000);
}

// branchless sorted-descending insert chains (IMNMX only)
__device__ __forceinline__ void chain4(uint32_t* L, uint32_t m) {
#pragma unroll
    for (int j = 0; j < 4; j++) {
        uint32_t mx = max(L[j], m);
        m = min(L[j], m);
        L[j] = mx;
    }
}
__device__ __forceinline__ void chain8(uint32_t* L, uint32_t m) {
#pragma unroll
    for (int j = 0; j < 8; j++) {
        uint32_t mx = max(L[j], m);
        m = min(L[j], m);
        L[j] = mx;
    }
}

// ---------------------------------------------------------------------------
// Kernel 1: persistent bf16 mma.sync GEMM + in-register group-max mining.
//   256 threads = 8 warps = 4 m-groups x 2 n-groups; warp tile 32(M) x 32(N),
//   two M-halves cover 256 x-rows. Block 0 additionally does prep work.
// ---------------------------------------------------------------------------
__global__ __launch_bounds__(256, 1)
void gemm_topk_kernel(const float* __restrict__ X, const float* __restrict__ Y,
                      const void* __restrict__ pos_inds, float* __restrict__ outp,
                      int N, int B) {
    extern __shared__ char smem[];
    __shared__ int s_not64;
    const uint32_t sb = smem_u32(smem);
    const int t    = threadIdx.x;
    const int lane = t & 31;
    const int wid  = t >> 5;
    const int wm   = wid >> 1;    // m-group 0..3
    const int ng   = wid & 1;     // n-group 0..1
    const int g    = lane >> 2;   // fragment row-within-8
    const int tg   = lane & 3;    // fragment col-pair
    const int bx   = blockIdx.x;

    // --- prep (block 0): zero out, sniff pos_inds dtype ---
    if (bx == 0 && t == 0) { outp[0] = 0.0f; s_not64 = 0; }
    __syncthreads();
    if (bx == 0 && t < B / 2) {
        long long v = ((const long long*)pos_inds)[t];
        if (v < 0 || v >= (long long)N) atomicExch(&s_not64, 1);
    }

    // --- load X (256x128 fp32 -> bf16) into swizzled SMEM ---
    {
        const float4* xs = (const float4*)X;
#pragma unroll
        for (int i = 0; i < 32; i++) {
            int fi = t + i * 256;
            int row = fi >> 5, c4 = fi & 31;
            float4 v = xs[fi];
            __nv_bfloat162 p0 = __float22bfloat162_rn(make_float2(v.x, v.y));
            __nv_bfloat162 p1 = __float22bfloat162_rn(make_float2(v.z, v.w));
            uint32_t off = XS_OFF + row * 256 +
                           (((c4 >> 1) ^ (row & 7)) << 4) + ((c4 & 1) << 3);
            *reinterpret_cast<uint2*>(smem + off) =
                make_uint2(*reinterpret_cast<uint32_t*>(&p0),
                           *reinterpret_cast<uint32_t*>(&p1));
        }
    }

    // --- prefetch + store first Y subtile into buffer 0 ---
    float4 pf[8];
    {
        const float4* ys = (const float4*)(Y + (size_t)bx * TN * DIM);
#pragma unroll
        for (int i = 0; i < 8; i++) pf[i] = ys[t + i * 256];
#pragma unroll
        for (int i = 0; i < 8; i++) {
            int fi = t + i * 256;
            int row = fi >> 5, c4 = fi & 31;
            __nv_bfloat162 p0 = __float22bfloat162_rn(make_float2(pf[i].x, pf[i].y));
            __nv_bfloat162 p1 = __float22bfloat162_rn(make_float2(pf[i].z, pf[i].w));
            uint32_t off = YS_OFF + row * 256 +
                           (((c4 >> 1) ^ (row & 7)) << 4) + ((c4 & 1) << 3);
            *reinterpret_cast<uint2*>(smem + off) =
                make_uint2(*reinterpret_cast<uint32_t*>(&p0),
                           *reinterpret_cast<uint32_t*>(&p1));
        }
    }
    __syncthreads();

    if (bx == 0 && t < B) {
        g_pos[t] = s_not64 ? ((const int*)pos_inds)[t]
                           : (int)((const long long*)pos_inds)[t];
    }

    // --- per-lane candidate lists: 8 rows (h,mt,rh), top-4 packed keys each ---
    uint32_t L[2][2][2][4];
#pragma unroll
    for (int h = 0; h < 2; h++)
#pragma unroll
        for (int mt = 0; mt < 2; mt++)
#pragma unroll
            for (int rh = 0; rh < 2; rh++)
#pragma unroll
                for (int j = 0; j < 4; j++) L[h][mt][rh][j] = 0;

    const int sub = lane >> 3, lr = lane & 7;
    const uint32_t gtag = (uint32_t)(ng * 4 + tg);   // low group bits
    int cb = 0;
    for (int st = bx; st < SUBT; st += GRIDX) {
        const int stn = st + GRIDX;
        const bool has_next = (stn < SUBT);

        if (has_next) {
            const float4* ys = (const float4*)(Y + (size_t)stn * TN * DIM);
#pragma unroll
            for (int i = 0; i < 8; i++) pf[i] = ys[t + i * 256];
        }

        const uint32_t ysb = sb + YS_OFF + cb * YS_SIZE;
        const uint32_t gid = (uint32_t)(st << 3) | gtag;   // group id, 14 bits

#pragma unroll
        for (int h = 0; h < 2; h++) {
            const int m0 = h * 128 + wm * 32;
            float acc[2][4][4];
#pragma unroll
            for (int mt = 0; mt < 2; mt++)
#pragma unroll
                for (int nt = 0; nt < 4; nt++)
#pragma unroll
                    for (int e = 0; e < 4; e++) acc[mt][nt][e] = 0.0f;

#pragma unroll
            for (int kt = 0; kt < 8; kt++) {
                uint32_t a[2][4], b[2][4];
                {
                    int rowa = m0 + ((sub & 1) << 3) + lr;
                    int ca   = 2 * kt + (sub >> 1);
#pragma unroll
                    for (int mt = 0; mt < 2; mt++) {
                        int row = rowa + mt * 16;
                        uint32_t addr = sb + XS_OFF + row * 256 +
                                        ((ca ^ (row & 7)) << 4);
                        ldsm_x4(a[mt], addr);
                    }
                }
                {
                    int rowb = ng * 32 + ((sub >> 1) << 3) + lr;
                    int cbk  = 2 * kt + (sub & 1);
#pragma unroll
                    for (int p = 0; p < 2; p++) {
                        int row = rowb + p * 16;
                        uint32_t addr = ysb + row * 256 + ((cbk ^ (row & 7)) << 4);
                        ldsm_x4(b[p], addr);
                    }
                }
#pragma unroll
                for (int mt = 0; mt < 2; mt++)
#pragma unroll
                    for (int nt = 0; nt < 4; nt++)
                        mma_bf16(acc[mt][nt], a[mt],
                                 b[nt >> 1][(nt & 1) * 2],
                                 b[nt >> 1][(nt & 1) * 2 + 1]);
            }

            // --- in-register scan: one group-max insert per (mt, rh) ---
#pragma unroll
            for (int mt = 0; mt < 2; mt++)
#pragma unroll
                for (int rh = 0; rh < 2; rh++) {
                    float v = fmaxf(
                        fmaxf(fmaxf(acc[mt][0][rh*2], acc[mt][0][rh*2+1]),
                              fmaxf(acc[mt][1][rh*2], acc[mt][1][rh*2+1])),
                        fmaxf(fmaxf(acc[mt][2][rh*2], acc[mt][2][rh*2+1]),
                              fmaxf(acc[mt][3][rh*2], acc[mt][3][rh*2+1])));
                    uint32_t pk = (fkey(v) & 0xFFFF0000u) | gid;
                    chain4(L[h][mt][rh], pk);
                }
        }

        if (has_next) {
            char* yd = smem + YS_OFF + (cb ^ 1) * YS_SIZE;
#pragma unroll
            for (int i = 0; i < 8; i++) {
                int fi = t + i * 256;
                int row = fi >> 5, c4 = fi & 31;
                __nv_bfloat162 p0 = __float22bfloat162_rn(make_float2(pf[i].x, pf[i].y));
                __nv_bfloat162 p1 = __float22bfloat162_rn(make_float2(pf[i].z, pf[i].w));
                uint32_t off = (uint32_t)(row * 256) +
                               (((c4 >> 1) ^ (row & 7)) << 4) + ((c4 & 1) << 3);
                *reinterpret_cast<uint2*>(yd + off) =
                    make_uint2(*reinterpret_cast<uint32_t*>(&p0),
                               *reinterpret_cast<uint32_t*>(&p1));
            }
        }
        cb ^= 1;
        __syncthreads();
    }

    // --- cross-tg butterfly merge, then lane tg==0 writes per (row, ng) top-4 ---
#pragma unroll
    for (int h = 0; h < 2; h++)
#pragma unroll
        for (int mt = 0; mt < 2; mt++)
#pragma unroll
            for (int rh = 0; rh < 2; rh++) {
                uint32_t* l = L[h][mt][rh];
#pragma unroll
                for (int xb = 1; xb <= 2; xb <<= 1) {
                    uint32_t o0 = __shfl_xor_sync(0xFFFFFFFFu, l[0], xb);
                    uint32_t o1 = __shfl_xor_sync(0xFFFFFFFFu, l[1], xb);
                    uint32_t o2 = __shfl_xor_sync(0xFFFFFFFFu, l[2], xb);
                    uint32_t o3 = __shfl_xor_sync(0xFFFFFFFFu, l[3], xb);
                    chain4(l, o0); chain4(l, o1); chain4(l, o2); chain4(l, o3);
                }
                if (tg == 0) {
                    int row = h * 128 + wm * 32 + mt * 16 + rh * 8 + g;
                    size_t base = (size_t)row * NC + (size_t)(bx * 2 + ng) * 4;
                    *reinterpret_cast<uint4*>(&g_cpack[base]) =
                        make_uint4(l[0], l[1], l[2], l[3]);
                }
            }
}

// ---------------------------------------------------------------------------
// Kernel 2: per-row merge -> top-NG groups -> exact fp32 rescore (120 elems +
//           pos) -> exact top-num_neg -> hinge + masked softmax -> atomicAdd
// ---------------------------------------------------------------------------
__global__ __launch_bounds__(128) void merge_loss_kernel(
    const float* __restrict__ X, const float* __restrict__ Y,
    const int* __restrict__ numneg_ptr, float* __restrict__ out,
    int N, int Btot)
{
    const int b = blockIdx.x;
    const int t = threadIdx.x;

    __shared__ float    xrow[DIM];
    __shared__ uint32_t cand[512];
    __shared__ uint32_t wtop[NG];
    __shared__ float    ex[121];
    __shared__ float    stop[KK];

    int num_neg = 5;
    if (numneg_ptr) {
        int nn = *numneg_ptr;
        if (nn >= 1 && nn <= KK) num_neg = nn;
    }
    const int pos = g_pos[b];

    xrow[t] = X[(size_t)b * DIM + t];

    // stage 1: per-thread top-4 packed candidates over strided subset (~9 each)
    {
        const uint32_t* cp = g_cpack + (size_t)b * NC;
        uint32_t M[4];
#pragma unroll
        for (int j = 0; j < 4; j++) M[j] = 0;
        for (int j = t; j < NC; j += 128) chain4(M, cp[j]);
#pragma unroll
        for (int j = 0; j < 4; j++) cand[t * 4 + j] = M[j];
    }
    __syncthreads();

    // stage 2: warp 0 selects global top-NG groups from 512 survivors
    if (t < 32) {
        uint32_t W[8];
#pragma unroll
        for (int j = 0; j < 8; j++) W[j] = 0;
#pragma unroll
        for (int k = 0; k < 16; k++) chain8(W, cand[t + (k << 5)]);
        int p = 0;
        for (int r = 0; r < NG; r++) {
            uint32_t head = (p < 8) ? W[p] : 0u;
            uint32_t w = head;
#pragma unroll
            for (int off = 16; off; off >>= 1) {
                uint32_t o = __shfl_xor_sync(0xFFFFFFFFu, w, off);
                w = (o > w) ? o : w;
            }
            if (head == w && w != 0u && p < 8) p++;
            if (t == 0) wtop[r] = w;
        }
    }
    __syncthreads();

    // rescore: NG groups x 8 elements + pos = 121 exact fp32 dots
    {
        int col = -1;
        if (t < NG * 8) {
            uint32_t w = wtop[t >> 3];
            if (w > 0xFFFFu) {
                int grp = (int)(w & 0x3FFFu);
                int stv = grp >> 3, ngv = (grp >> 2) & 1, tgv = grp & 3;
                int e = t & 7;
                col = stv * 64 + ngv * 32 + ((e >> 1) << 3) + tgv * 2 + (e & 1);
                if (col == pos) col = -1;
            }
        } else if (t == NG * 8) {
            col = pos;
        }
        if (t <= NG * 8) {
            float d = NEGF;
            if (col >= 0 && col < N) {
                const float4* yr = (const float4*)(Y + (size_t)col * DIM);
                const float4* xr = (const float4*)xrow;
                d = 0.0f;
#pragma unroll
                for (int k = 0; k < 32; k++) {
                    float4 yv = yr[k], xv = xr[k];
                    d = fmaf(xv.x, yv.x, d);
                    d = fmaf(xv.y, yv.y, d);
                    d = fmaf(xv.z, yv.z, d);
                    d = fmaf(xv.w, yv.w, d);
                }
            }
            ex[t] = d;
        }
    }
    __syncthreads();

    // exact top-8 of ex[0..119] via warp 0 (float compare, idx tie-break)
    if (t < 32) {
        float v[4];
        int   id[4];
#pragma unroll
        for (int j = 0; j < 4; j++) {
            int p2 = t * 4 + j;
            v[j]  = (p2 < NG * 8) ? ex[p2] : NEGF;
            id[j] = p2;
        }
#pragma unroll
        for (int a = 0; a < 4; a++)
#pragma unroll
            for (int c = a + 1; c < 4; c++)
                if (v[c] > v[a] || (v[c] == v[a] && id[c] < id[a])) {
                    float tv = v[a]; v[a] = v[c]; v[c] = tv;
                    int   ti = id[a]; id[a] = id[c]; id[c] = ti;
                }
        int p = 0;
        for (int r = 0; r < KK; r++) {
            float hv = (p < 4) ? v[p] : NEGF;
            int   hi = (p < 4) ? id[p] : 1000 + t;
            float wv = hv; int wi = hi;
#pragma unroll
            for (int off = 16; off; off >>= 1) {
                float ov = __shfl_xor_sync(0xFFFFFFFFu, wv, off);
                int   oi = __shfl_xor_sync(0xFFFFFFFFu, wi, off);
                if (ov > wv || (ov == wv && oi < wi)) { wv = ov; wi = oi; }
            }
            if (hi == wi && p < 4) p++;
            if (t == 0) stop[r] = wv;
        }
    }
    __syncthreads();

    if (t == 0) {
        float sim_p = ex[NG * 8];
        float loss[KK], m[KK], mx = NEGF;
        for (int r = 0; r < num_neg; r++) {
            float sn = stop[r];
            float l = sn - sim_p + 0.3f;
            l = (l > 0.0f) ? l : 0.0f;
            float mm = (l != 0.0f) ? sn : 0.0f;
            loss[r] = l; m[r] = mm;
            if (mm > mx) mx = mm;
        }
        float ssum = 0.0f, res = 0.0f;
        float e[KK];
        for (int r = 0; r < num_neg; r++) { e[r] = expf(m[r] - mx); ssum += e[r]; }
        for (int r = 0; r < num_neg; r++) res += loss[r] * e[r];
        res /= ssum;
        atomicAdd(out, res / ((float)Btot * (float)num_neg));
    }
}

// ---------------------------------------------------------------------------
// kernel_launch
// ---------------------------------------------------------------------------
extern "C" void kernel_launch(void* const* d_in, const int* in_sizes, int n_in,
                              void* d_out, int out_size)
{
    const float* xembs  = (const float*)d_in[0];
    const float* yembs  = (const float*)d_in[1];
    const void*  posind = d_in[3];
    const int*   numneg = (n_in >= 5) ? (const int*)d_in[4] : nullptr;

    const int B = in_sizes[0] / DIM;   // 256
    const int N = in_sizes[1] / DIM;   // 131072
    float* out = (float*)d_out;

    static int smem_set = 0;
    if (!smem_set) {
        cudaFuncSetAttribute(gemm_topk_kernel,
                             cudaFuncAttributeMaxDynamicSharedMemorySize,
                             SMEM_TOTAL);
        smem_set = 1;
    }
    gemm_topk_kernel<<<GRIDX, 256, SMEM_TOTAL>>>(xembs, yembs, posind, out, N, B);
    merge_loss_kernel<<<B, 128>>>(xembs, yembs, numneg, out, N, B);
}